// round 7
// baseline (speedup 1.0000x reference)
#include <cuda_runtime.h>
#include <cuda_bf16.h>
#include <math.h>

#define KC 64
#define DD 128
#define NN 4096
#define NB 16
#define GRID (NN / NB)   // 256 blocks, all co-resident (occupancy >= 2/SM)
#define MPAD 129         // padded smem row stride: conflict-free both access patterns

#define LN2F 0.6931471805599453f
#define LOG2PIF 1.8378770664093453f      // log(2*pi)
#define LGAMMA64F 201.00931639928152f    // lgamma(64)

// ---------------- device scratch (zero-init; self-resetting each run) ----------------
__device__ float g_sums[KC * DD];
__device__ float g_counts[KC];
__device__ float g_numer[KC * KC];
__device__ float g_rank;
__device__ float g_js;
__device__ int   g_arrive;   // software grid barrier
__device__ int   g_done;     // epilogue completion counter

__device__ __forceinline__ float softplus_precise(float x) {
    return (x > 0.0f) ? (x + log1pf(expf(-x))) : log1pf(expf(x));
}

// ---------------- single fused kernel ----------------
__global__ void __launch_bounds__(256) k_fused(const float* __restrict__ feat,
                                               const float* __restrict__ musp,
                                               const float* __restrict__ rho,
                                               const int* __restrict__ lab32,
                                               float* __restrict__ out) {
    __shared__ float mus_sh[KC * MPAD];              // raw mus, padded (33KB)
    __shared__ __align__(16) float f[NB][DD];        // 8KB
    __shared__ float Lsh[NB][KC];                    // 4KB
    __shared__ float invn[NB];
    __shared__ float invmu[KC], kap_sh[KC], lc_sh[KC];
    __shared__ float musq[4][KC];
    __shared__ int lab[NB];
    int tid = threadIdx.x;
    int bid = blockIdx.x;
    int n0 = bid * NB;

    // labels dtype probe (odd int32 words nonzero => int32 labels)
    int pred = (lab32[2 * tid + 1] != 0);

    // load mus_param coalesced -> padded rows
    {
        const float4* msrc = (const float4*)musp;
#pragma unroll
        for (int r = 0; r < 8; r++) {
            int idx = tid + 256 * r;
            float4 v = msrc[idx];
            int k = idx >> 5, d = (idx & 31) * 4;
            float* p = &mus_sh[k * MPAD + d];
            p[0] = v.x; p[1] = v.y; p[2] = v.z; p[3] = v.w;
        }
    }
    // load features
    {
        const float4* src = (const float4*)(feat + n0 * DD);
        float4* dst = (float4*)&f[0][0];
        dst[tid]       = src[tid];
        dst[tid + 256] = src[tid + 256];
    }
    int anyodd = __syncthreads_or(pred);

    if (tid < NB) {
        int shift = anyodd ? 0 : 1;
        int l = lab32[(n0 + tid) << shift];
        lab[tid] = min(max(l, 0), KC - 1);
    }

    // mus squared-norm partials
    {
        int k = tid & 63, q = tid >> 6;
        float s = 0.0f;
#pragma unroll
        for (int r = 0; r < 32; r++) {
            float m = mus_sh[k * MPAD + q * 32 + r];
            s += m * m;
        }
        musq[q][k] = s;
    }
    // feature norms
    {
        int w = tid >> 5, lane = tid & 31;
#pragma unroll
        for (int rr = 0; rr < 2; rr++) {
            int r = 2 * w + rr;
            float s = 0.0f;
#pragma unroll
            for (int c = 0; c < 4; c++) {
                float x = f[r][lane + 32 * c];
                s += x * x;
            }
#pragma unroll
            for (int o = 16; o > 0; o >>= 1) s += __shfl_xor_sync(0xffffffffu, s, o);
            if (lane == 0) invn[r] = 1.0f / fmaxf(sqrtf(s), 1e-12f);
        }
    }
    __syncthreads();

    // per-class scalars
    if (tid < KC) {
        float s = musq[0][tid] + musq[1][tid] + musq[2][tid] + musq[3][tid];
        invmu[tid] = 1.0f / fmaxf(sqrtf(s), 1e-12f);
        float r = rho[tid];
        float kap = fmaxf(softplus_precise(r), 1e-6f);
        kap_sh[tid] = kap;
        float logI = (kap < 1e-3f)
                   ? 63.0f * logf(kap * 0.5f + 1e-12f) - LGAMMA64F
                   : kap - 0.5f * logf(6.283185307179586f * kap + 1e-12f);
        lc_sh[tid] = -63.0f * logf(kap + 1e-12f) - 64.0f * LOG2PIF - logI;
    }
    __syncthreads();

    // class sums + counts (global atomics, spread addresses)
    {
        int d = tid & 127, half = tid >> 7;
#pragma unroll
        for (int nn = 0; nn < 8; nn++) {
            int n = half * 8 + nn;
            atomicAdd(&g_sums[lab[n] * DD + d], f[n][d] * invn[n]);
        }
    }
    if (tid < NB) atomicAdd(&g_counts[lab[tid]], 1.0f);

    // L = logC + kappa*invmu*invn*(f . mu_raw); 4 samples per thread
    int g = tid >> 6;
    int k = tid & 63;
    float acc0 = 0.f, acc1 = 0.f, acc2 = 0.f, acc3 = 0.f;
    const float4* f0 = (const float4*)&f[g * 4 + 0][0];
    const float4* f1 = (const float4*)&f[g * 4 + 1][0];
    const float4* f2 = (const float4*)&f[g * 4 + 2][0];
    const float4* f3 = (const float4*)&f[g * 4 + 3][0];
    const float* mrow = &mus_sh[k * MPAD];
#pragma unroll
    for (int d4 = 0; d4 < DD / 4; d4++) {
        float m0 = mrow[4 * d4 + 0];
        float m1 = mrow[4 * d4 + 1];
        float m2 = mrow[4 * d4 + 2];
        float m3 = mrow[4 * d4 + 3];
        float4 x0 = f0[d4], x1 = f1[d4], x2 = f2[d4], x3 = f3[d4];
        acc0 += m0 * x0.x + m1 * x0.y + m2 * x0.z + m3 * x0.w;
        acc1 += m0 * x1.x + m1 * x1.y + m2 * x1.z + m3 * x1.w;
        acc2 += m0 * x2.x + m1 * x2.y + m2 * x2.z + m3 * x2.w;
        acc3 += m0 * x3.x + m1 * x3.y + m2 * x3.z + m3 * x3.w;
    }
    float sk = kap_sh[k] * invmu[k], lc = lc_sh[k];
    Lsh[g * 4 + 0][k] = lc + sk * invn[g * 4 + 0] * acc0;
    Lsh[g * 4 + 1][k] = lc + sk * invn[g * 4 + 1] * acc1;
    Lsh[g * 4 + 2][k] = lc + sk * invn[g * 4 + 2] * acc2;
    Lsh[g * 4 + 3][k] = lc + sk * invn[g * 4 + 3] * acc3;
    __syncthreads();

    // numer_pi[label_n][k] += ln2 - softplus(L[n,k] - L[n,label_n])
#pragma unroll
    for (int nn = 0; nn < 4; nn++) {
        int n = g * 4 + nn;
        float x = Lsh[n][k] - Lsh[n][lab[n]];
        float sp = __logf(1.0f + __expf(-fabsf(x))) + fmaxf(x, 0.0f);
        atomicAdd(&g_numer[lab[n] * KC + k], LN2F - sp);
    }

    // ---------------- software grid barrier (all 256 blocks co-resident) ----------------
    __threadfence();            // release this thread's atomics device-wide
    __syncthreads();
    if (tid == 0) atomicAdd(&g_arrive, 1);
    if (bid >= KC) return;      // blocks 64..255 done

    if (tid == 0) {
        volatile int* va = &g_arrive;
        while (*va < GRID) { }
    }
    __syncthreads();
    __threadfence();            // acquire

    // ---------------- epilogue: rank + js for row i = bid (mus still in smem) ----------------
    int i = bid;
    // repurpose smem
    float* mean_sh = &f[0][0];            // 128 floats
    float* cnts    = &f[2][0];            // 64
    float* numr    = &f[3][0];            // 64
    float* A_s     = &f[4][0];            // 64
    float (*pdm)[KC] = (float(*)[KC])&Lsh[0][0];   // 4x64
    float (*pdu)[KC] = (float(*)[KC])&Lsh[4][0];   // 4x64
    float* dotm    = &Lsh[8][0];
    float* dotu    = &Lsh[9][0];
    float* redr    = &Lsh[10][0];
    float* redj    = &Lsh[11][0];

    if (tid < KC) {
        cnts[tid] = g_counts[tid];
        numr[tid] = g_numer[i * KC + tid];
        float kap = kap_sh[tid];
        float kc = fmaxf(kap, 1e-8f);
        A_s[tid] = (kc > 50.0f) ? (1.0f - 127.0f / (2.0f * kc)) : (kc / 128.0f);
    }
    __syncthreads();

    float cnt_i = cnts[i];
    bool zi = (cnt_i == 0.0f);
    float cs = fmaxf(cnt_i, 1.0f);
    if (tid < DD)
        mean_sh[tid] = zi ? mus_sh[i * MPAD + tid] * invmu[i]
                          : (g_sums[i * DD + tid] / cs);
    __syncthreads();
    // self-reset rows owned by this block
    if (tid < DD) g_sums[i * DD + tid] = 0.0f;
    if (tid < KC) g_numer[i * KC + tid] = 0.0f;

    // dots: thread (j, quarter); raw mus scaled by invmu at combine
    {
        int j = tid & 63, q = tid >> 6;
        float dm = 0.0f, du = 0.0f;
        const float* mi = &mus_sh[i * MPAD + q * 32];
        const float* mj = &mus_sh[j * MPAD + q * 32];
        const float* me = &mean_sh[q * 32];
#pragma unroll
        for (int r = 0; r < 32; r++) {
            float m = mj[r];
            dm += me[r] * m;
            du += mi[r] * m;
        }
        pdm[q][j] = dm;
        pdu[q][j] = du;
    }
    __syncthreads();
    if (tid < KC) {
        dotm[tid] = (pdm[0][tid] + pdm[1][tid] + pdm[2][tid] + pdm[3][tid]) * invmu[tid];
        dotu[tid] = (pdu[0][tid] + pdu[1][tid] + pdu[2][tid] + pdu[3][tid]) * invmu[i] * invmu[tid];
    }
    __syncthreads();

    if (tid < KC) {
        int j = tid;
        float diff = kap_sh[i] * dotm[i] - kap_sh[j] * dotm[j];
        float h = (j != i) ? fmaxf(0.5f * fabsf((float)(i - j)) - diff, 0.0f) / cs : 0.0f;
        float cnt_j = cnts[j];
        bool zp = zi || (cnt_j == 0.0f);
        float wgt = (i == j) ? 0.0f : fabsf((float)(i - j));
        float contrib;
        if (zp) {
            float ki = kap_sh[i], kj = kap_sh[j];
            contrib = wgt * 0.5f * (A_s[i] * (ki - kj * dotu[j]) + A_s[j] * (kj - ki * dotu[j]));
        } else {
            contrib = wgt * numr[j] / cs;   // symmetry-folded JS
        }
        redr[j] = h;
        redj[j] = contrib;
    }
    __syncthreads();
    if (tid < 32) {
        float r = redr[tid] + redr[tid + 32];
        float jj = redj[tid] + redj[tid + 32];
#pragma unroll
        for (int o = 16; o > 0; o >>= 1) {
            r  += __shfl_xor_sync(0xffffffffu, r, o);
            jj += __shfl_xor_sync(0xffffffffu, jj, o);
        }
        if (tid == 0) {
            atomicAdd(&g_rank, r);
            atomicAdd(&g_js, jj);
            __threadfence();
            if (atomicAdd(&g_done, 1) == KC - 1) {
                float rr = atomicAdd(&g_rank, 0.0f);
                float ss = atomicAdd(&g_js, 0.0f);
                out[0] = rr / (4096.0f + 1e-9f) + ss / (87360.0f + 1e-9f);
                // reset shared state for next graph replay
                for (int c = 0; c < KC; c++) g_counts[c] = 0.0f;
                g_rank = 0.0f; g_js = 0.0f; g_done = 0; g_arrive = 0;
            }
        }
    }
}

extern "C" void kernel_launch(void* const* d_in, const int* in_sizes, int n_in,
                              void* d_out, int out_size) {
    const float* features  = (const float*)d_in[0];
    const float* mus_param = (const float*)d_in[1];
    const float* rho_kappa = (const float*)d_in[2];
    const int*   labels32  = (const int*)d_in[3];
    float* out = (float*)d_out;

    k_fused<<<GRID, 256>>>(features, mus_param, rho_kappa, labels32, out);
}